// round 1
// baseline (speedup 1.0000x reference)
#include <cuda_runtime.h>

#define NB   128
#define NPG  1024
#define NN   (NB*NPG)      // 131072 nodes
#define NE   (NN*8)        // 1048576 edges
#define DLAT 97
#define KTOP 30
#define C1   16
#define C2   32
#define KW2  5
#define OUTC 2

// scratch (device globals — no allocation allowed)
__device__ float g_deg[NN];
__device__ float g_e2n[NN*32];
__device__ float g_feat[NN*DLAT];   // concat(h0,h1,h2,h3) row-major [N][97]
__device__ float g_Y[NN*32];
__device__ float g_Z[NN*32];

__device__ __forceinline__ void red_add_v4(float* addr, float4 v){
    asm volatile("red.global.add.v4.f32 [%0], {%1,%2,%3,%4};"
        :: "l"(addr), "f"(v.x), "f"(v.y), "f"(v.z), "f"(v.w) : "memory");
}

__global__ void k_init(){
    int idx = blockIdx.x*blockDim.x + threadIdx.x;
    if (idx < NN) g_deg[idx] = 1.0f;
    if (idx < NN*32) g_e2n[idx] = 0.0f;
}

// e2n = segment_sum(edge_feat, dst); deg = 1 + indegree
__global__ void k_edge(const float* __restrict__ ef, const int* __restrict__ ei){
    int idx = blockIdx.x*blockDim.x + threadIdx.x;
    if (idx >= NE*8) return;
    int e = idx >> 3, q = idx & 7;
    int dst = __ldg(&ei[NE + e]);
    float4 v = reinterpret_cast<const float4*>(ef)[idx];
    red_add_v4(&g_e2n[dst*32 + q*4], v);
    if (q == 0) atomicAdd(&g_deg[dst], 1.0f);
}

__global__ void k_zero(int count){
    int idx = blockIdx.x*blockDim.x + threadIdx.x;
    if (idx < count) g_Z[idx] = 0.0f;
}

// Y = [node_feat | e2n] @ W0   (160 -> 32), warp per row, W in smem
__global__ void k_gemm0(const float* __restrict__ nf, const float* __restrict__ W){
    __shared__ float sW[160*32];
    int tid = threadIdx.x;
    for (int i = tid; i < 160*32; i += blockDim.x) sW[i] = W[i];
    __syncthreads();
    int lane = tid & 31, warp = tid >> 5;
    int row = blockIdx.x*8 + warp;
    float acc = 0.f;
    #pragma unroll
    for (int ch = 0; ch < 4; ch++){
        float x = nf[row*128 + ch*32 + lane];
        #pragma unroll
        for (int kk = 0; kk < 32; kk++){
            float xv = __shfl_sync(0xffffffffu, x, kk);
            acc = fmaf(xv, sW[(ch*32+kk)*32 + lane], acc);
        }
    }
    {
        float x = g_e2n[row*32 + lane];
        #pragma unroll
        for (int kk = 0; kk < 32; kk++){
            float xv = __shfl_sync(0xffffffffu, x, kk);
            acc = fmaf(xv, sW[(128+kk)*32 + lane], acc);
        }
    }
    g_Y[row*32 + lane] = acc;
}

// Y = feat[:, in_off:in_off+32] @ W   (32 -> 32)
__global__ void k_gemm32(const float* __restrict__ W, int in_off){
    __shared__ float sW[32*32];
    int tid = threadIdx.x;
    for (int i = tid; i < 32*32; i += blockDim.x) sW[i] = W[i];
    __syncthreads();
    int lane = tid & 31, warp = tid >> 5;
    int row = blockIdx.x*8 + warp;
    float x = g_feat[row*DLAT + in_off + lane];
    float acc = 0.f;
    #pragma unroll
    for (int kk = 0; kk < 32; kk++){
        float xv = __shfl_sync(0xffffffffu, x, kk);
        acc = fmaf(xv, sW[kk*32 + lane], acc);
    }
    g_Y[row*32 + lane] = acc;
}

// Z[dst] += Y[src], width 32, vector-4 reductions
__global__ void k_scatter32(const int* __restrict__ ei){
    int idx = blockIdx.x*blockDim.x + threadIdx.x;
    if (idx >= NE*8) return;
    int e = idx >> 3, q = idx & 7;
    int src = __ldg(&ei[e]);
    int dst = __ldg(&ei[NE + e]);
    float4 v = reinterpret_cast<const float4*>(g_Y)[src*8 + q];
    red_add_v4(&g_Z[dst*32 + q*4], v);
}

// feat[:, out_off:out_off+32] = tanh((Z + Y + b) / deg)
__global__ void k_finish32(const float* __restrict__ bias, int out_off){
    int idx = blockIdx.x*blockDim.x + threadIdx.x;
    if (idx >= NN*32) return;
    int n = idx >> 5, f = idx & 31;
    float v = (g_Z[idx] + g_Y[idx] + bias[f]) / g_deg[n];
    g_feat[n*DLAT + out_off + f] = tanhf(v);
}

// Y1[n] = h2[n,:] @ W3   (32 -> 1), warp per row
__global__ void k_matvec(const float* __restrict__ W3){
    int tid = threadIdx.x;
    int lane = tid & 31, warp = tid >> 5;
    int row = blockIdx.x*8 + warp;
    float v = g_feat[row*DLAT + 64 + lane] * W3[lane];
    #pragma unroll
    for (int s = 16; s > 0; s >>= 1) v += __shfl_xor_sync(0xffffffffu, v, s);
    if (lane == 0) g_Y[row] = v;
}

__global__ void k_scatter1(const int* __restrict__ ei){
    int e = blockIdx.x*blockDim.x + threadIdx.x;
    if (e >= NE) return;
    atomicAdd(&g_Z[__ldg(&ei[NE+e])], g_Y[__ldg(&ei[e])]);
}

__global__ void k_finish1(const float* __restrict__ b3){
    int n = blockIdx.x*blockDim.x + threadIdx.x;
    if (n >= NN) return;
    g_feat[n*DLAT + 96] = tanhf((g_Z[n] + g_Y[n] + b3[0]) / g_deg[n]);
}

// one block per graph: bitonic top-k sort, gather, conv1+pool+conv2+dense
__global__ void k_head(const float* __restrict__ wc1, const float* __restrict__ bc1,
                       const float* __restrict__ wc2, const float* __restrict__ bc2,
                       const float* __restrict__ wout, const float* __restrict__ bout,
                       float* __restrict__ out){
    __shared__ float s_val[NPG];
    __shared__ int   s_idx[NPG];
    __shared__ float s_sp[KTOP*DLAT];
    __shared__ float s_w1[C1*DLAT];
    __shared__ float s_t1[C1*30];
    __shared__ float s_p[C1*15];
    __shared__ float s_q[C2*11];
    int b = blockIdx.x, tid = threadIdx.x;
    for (int i = tid; i < NPG; i += blockDim.x){
        s_val[i] = g_feat[(b*NPG + i)*DLAT + 96];
        s_idx[i] = i;
    }
    for (int i = tid; i < C1*DLAT; i += blockDim.x) s_w1[i] = wc1[i];
    __syncthreads();
    // bitonic sort: descending by val, ties -> ascending index (lax.top_k semantics)
    for (int k = 2; k <= NPG; k <<= 1){
        for (int j = k >> 1; j > 0; j >>= 1){
            for (int i = tid; i < NPG; i += blockDim.x){
                int ixj = i ^ j;
                if (ixj > i){
                    float va = s_val[i], vb = s_val[ixj];
                    int ia = s_idx[i], ib = s_idx[ixj];
                    bool before_ba = (vb > va) || (vb == va && ib < ia);
                    bool up = ((i & k) == 0);
                    if (up ? before_ba : !before_ba){
                        s_val[i] = vb; s_val[ixj] = va;
                        s_idx[i] = ib; s_idx[ixj] = ia;
                    }
                }
            }
            __syncthreads();
        }
    }
    // gather top-30 feature rows
    for (int t = tid; t < KTOP*DLAT; t += blockDim.x){
        int kk = t / DLAT, d = t % DLAT;
        int node = b*NPG + s_idx[kk];
        s_sp[t] = g_feat[node*DLAT + d];
    }
    __syncthreads();
    // conv1 (kernel=stride=97 -> per-node dot) + relu -> [16][30]
    for (int t = tid; t < C1*30; t += blockDim.x){
        int c = t / 30, j = t % 30;
        float acc = bc1[c];
        for (int d = 0; d < DLAT; d++) acc = fmaf(s_sp[j*DLAT + d], s_w1[c*DLAT + d], acc);
        s_t1[t] = fmaxf(acc, 0.f);
    }
    __syncthreads();
    // maxpool(2,2) -> [16][15]
    for (int t = tid; t < C1*15; t += blockDim.x){
        int c = t / 15, l = t % 15;
        s_p[t] = fmaxf(s_t1[c*30 + 2*l], s_t1[c*30 + 2*l + 1]);
    }
    __syncthreads();
    // conv2 (16->32, k=5) + relu -> [32][11]
    for (int t = tid; t < C2*11; t += blockDim.x){
        int c2 = t / 11, l = t % 11;
        float acc = bc2[c2];
        for (int c1 = 0; c1 < C1; c1++)
            #pragma unroll
            for (int tt = 0; tt < KW2; tt++)
                acc = fmaf(s_p[c1*15 + l + tt], wc2[(c2*C1 + c1)*KW2 + tt], acc);
        s_q[t] = fmaxf(acc, 0.f);
    }
    __syncthreads();
    // dense [352 -> 2] + relu
    if (tid < 64){
        int o = tid >> 5, lane = tid & 31;
        float acc = 0.f;
        for (int i = lane; i < C2*11; i += 32) acc = fmaf(s_q[i], wout[i*OUTC + o], acc);
        #pragma unroll
        for (int s = 16; s > 0; s >>= 1) acc += __shfl_xor_sync(0xffffffffu, acc, s);
        if (lane == 0) out[b*OUTC + o] = fmaxf(acc + bout[o], 0.f);
    }
}

extern "C" void kernel_launch(void* const* d_in, const int* in_sizes, int n_in,
                              void* d_out, int out_size){
    const float* nf   = (const float*)d_in[0];
    const float* ef   = (const float*)d_in[1];
    const int*   ei   = (const int*)  d_in[2];
    const float* W0   = (const float*)d_in[3];
    const float* b0   = (const float*)d_in[4];
    const float* W1   = (const float*)d_in[5];
    const float* b1   = (const float*)d_in[6];
    const float* W2   = (const float*)d_in[7];
    const float* b2   = (const float*)d_in[8];
    const float* W3   = (const float*)d_in[9];
    const float* b3   = (const float*)d_in[10];
    const float* wc1  = (const float*)d_in[11];
    const float* bc1  = (const float*)d_in[12];
    const float* wc2  = (const float*)d_in[13];
    const float* bc2  = (const float*)d_in[14];
    const float* wout = (const float*)d_in[15];
    const float* bout = (const float*)d_in[16];
    float* out = (float*)d_out;

    const int T = 256;
    k_init<<<(NN*32 + T-1)/T, T>>>();
    k_edge<<<(NE*8 + T-1)/T, T>>>(ef, ei);
    // hop 0: 160 -> 32
    k_zero<<<(NN*32 + T-1)/T, T>>>(NN*32);
    k_gemm0<<<NN/8, 256>>>(nf, W0);
    k_scatter32<<<(NE*8 + T-1)/T, T>>>(ei);
    k_finish32<<<(NN*32 + T-1)/T, T>>>(b0, 0);
    // hop 1: 32 -> 32
    k_zero<<<(NN*32 + T-1)/T, T>>>(NN*32);
    k_gemm32<<<NN/8, 256>>>(W1, 0);
    k_scatter32<<<(NE*8 + T-1)/T, T>>>(ei);
    k_finish32<<<(NN*32 + T-1)/T, T>>>(b1, 32);
    // hop 2: 32 -> 32
    k_zero<<<(NN*32 + T-1)/T, T>>>(NN*32);
    k_gemm32<<<NN/8, 256>>>(W2, 32);
    k_scatter32<<<(NE*8 + T-1)/T, T>>>(ei);
    k_finish32<<<(NN*32 + T-1)/T, T>>>(b2, 64);
    // hop 3: 32 -> 1
    k_zero<<<(NN + T-1)/T, T>>>(NN);
    k_matvec<<<NN/8, 256>>>(W3);
    k_scatter1<<<(NE + T-1)/T, T>>>(ei);
    k_finish1<<<(NN + T-1)/T, T>>>(b3);
    // sort-pool + conv head
    k_head<<<NB, 256>>>(wc1, bc1, wc2, bc2, wout, bout, out);
}

// round 2
// speedup vs baseline: 1.4543x; 1.4543x over previous
#include <cuda_runtime.h>

#define NB   128
#define NPG  1024
#define NN   (NB*NPG)      // 131072 nodes
#define NE   (NN*8)        // 1048576 edges
#define DLAT 97
#define KTOP 30
#define C1   16
#define C2   32
#define KW2  5
#define OUTC 2

// scratch (device globals — no allocation allowed)
__device__ float g_deg[NN];
__device__ float g_e2n[NN*32];
__device__ float g_feat[NN*DLAT];   // concat(h0,h1,h2,h3) row-major [N][97]
__device__ float g_Y[NN*32];
__device__ float g_Z[NN*32];

__device__ __forceinline__ void red_add_v4(float* addr, float4 v){
    asm volatile("red.global.add.v4.f32 [%0], {%1,%2,%3,%4};"
        :: "l"(addr), "f"(v.x), "f"(v.y), "f"(v.z), "f"(v.w) : "memory");
}

__global__ void k_init(){
    int idx = blockIdx.x*blockDim.x + threadIdx.x;
    if (idx < NN) g_deg[idx] = 1.0f;
    if (idx < NN*32) g_e2n[idx] = 0.0f;
}

// e2n = segment_sum(edge_feat, dst); deg = 1 + indegree
__global__ void k_edge(const float* __restrict__ ef, const int* __restrict__ ei){
    int idx = blockIdx.x*blockDim.x + threadIdx.x;
    if (idx >= NE*8) return;
    int e = idx >> 3, q = idx & 7;
    int dst = __ldg(&ei[NE + e]);
    float4 v = reinterpret_cast<const float4*>(ef)[idx];
    red_add_v4(&g_e2n[dst*32 + q*4], v);
    if (q == 0) atomicAdd(&g_deg[dst], 1.0f);
}

__global__ void k_zero(int count){
    int idx = blockIdx.x*blockDim.x + threadIdx.x;
    if (idx < count) g_Z[idx] = 0.0f;
}

// ---------------------------------------------------------------------------
// Register-tiled GEMM: Y[128 rows x 32 cols per block] = X @ W
// block = 256 threads, thread tile = 4 rows x 4 cols.
// Per k-step: 4 broadcast LDS (X) + 1 LDS.128 (W) + 16 FMA  -> FMA bound.
// ---------------------------------------------------------------------------

// hop 0: X = [node_feat(128) | e2n(32)]  (K=160), W0 [160][32]
__global__ __launch_bounds__(256) void k_gemm0(const float* __restrict__ nf,
                                               const float* __restrict__ W){
    __shared__ float sX[128][33];
    __shared__ float sW[160*32];
    int tid = threadIdx.x;
    int rowbase = blockIdx.x*128;
    for (int i = tid; i < 160*32; i += 256) sW[i] = W[i];
    int c0 = (tid & 7)*4, r0 = (tid >> 3)*4;
    float acc[4][4];
    #pragma unroll
    for (int i=0;i<4;i++)
        #pragma unroll
        for (int j=0;j<4;j++) acc[i][j]=0.f;

    for (int kc = 0; kc < 160; kc += 32){
        __syncthreads();
        for (int i = tid; i < 128*32; i += 256){
            int r = i >> 5, k = i & 31;
            float v = (kc < 128) ? nf[(rowbase+r)*128 + kc + k]
                                 : g_e2n[(rowbase+r)*32 + k];
            sX[r][k] = v;
        }
        __syncthreads();
        #pragma unroll
        for (int k = 0; k < 32; k++){
            float4 w = *(const float4*)&sW[(kc+k)*32 + c0];
            float x0=sX[r0][k], x1=sX[r0+1][k], x2=sX[r0+2][k], x3=sX[r0+3][k];
            acc[0][0]=fmaf(x0,w.x,acc[0][0]); acc[0][1]=fmaf(x0,w.y,acc[0][1]);
            acc[0][2]=fmaf(x0,w.z,acc[0][2]); acc[0][3]=fmaf(x0,w.w,acc[0][3]);
            acc[1][0]=fmaf(x1,w.x,acc[1][0]); acc[1][1]=fmaf(x1,w.y,acc[1][1]);
            acc[1][2]=fmaf(x1,w.z,acc[1][2]); acc[1][3]=fmaf(x1,w.w,acc[1][3]);
            acc[2][0]=fmaf(x2,w.x,acc[2][0]); acc[2][1]=fmaf(x2,w.y,acc[2][1]);
            acc[2][2]=fmaf(x2,w.z,acc[2][2]); acc[2][3]=fmaf(x2,w.w,acc[2][3]);
            acc[3][0]=fmaf(x3,w.x,acc[3][0]); acc[3][1]=fmaf(x3,w.y,acc[3][1]);
            acc[3][2]=fmaf(x3,w.z,acc[3][2]); acc[3][3]=fmaf(x3,w.w,acc[3][3]);
        }
    }
    #pragma unroll
    for (int i = 0; i < 4; i++){
        float4 v = make_float4(acc[i][0],acc[i][1],acc[i][2],acc[i][3]);
        *(float4*)&g_Y[(rowbase + r0 + i)*32 + c0] = v;
    }
}

// hops 1/2: X = feat[:, in_off:in_off+32]  (K=32)
__global__ __launch_bounds__(256) void k_gemm32(const float* __restrict__ W, int in_off){
    __shared__ float sX[128][33];
    __shared__ float sW[32*32];
    int tid = threadIdx.x;
    int rowbase = blockIdx.x*128;
    for (int i = tid; i < 32*32; i += 256) sW[i] = W[i];
    for (int i = tid; i < 128*32; i += 256){
        int r = i >> 5, k = i & 31;
        sX[r][k] = g_feat[(rowbase+r)*DLAT + in_off + k];
    }
    int c0 = (tid & 7)*4, r0 = (tid >> 3)*4;
    float acc[4][4];
    #pragma unroll
    for (int i=0;i<4;i++)
        #pragma unroll
        for (int j=0;j<4;j++) acc[i][j]=0.f;
    __syncthreads();
    #pragma unroll
    for (int k = 0; k < 32; k++){
        float4 w = *(const float4*)&sW[k*32 + c0];
        float x0=sX[r0][k], x1=sX[r0+1][k], x2=sX[r0+2][k], x3=sX[r0+3][k];
        acc[0][0]=fmaf(x0,w.x,acc[0][0]); acc[0][1]=fmaf(x0,w.y,acc[0][1]);
        acc[0][2]=fmaf(x0,w.z,acc[0][2]); acc[0][3]=fmaf(x0,w.w,acc[0][3]);
        acc[1][0]=fmaf(x1,w.x,acc[1][0]); acc[1][1]=fmaf(x1,w.y,acc[1][1]);
        acc[1][2]=fmaf(x1,w.z,acc[1][2]); acc[1][3]=fmaf(x1,w.w,acc[1][3]);
        acc[2][0]=fmaf(x2,w.x,acc[2][0]); acc[2][1]=fmaf(x2,w.y,acc[2][1]);
        acc[2][2]=fmaf(x2,w.z,acc[2][2]); acc[2][3]=fmaf(x2,w.w,acc[2][3]);
        acc[3][0]=fmaf(x3,w.x,acc[3][0]); acc[3][1]=fmaf(x3,w.y,acc[3][1]);
        acc[3][2]=fmaf(x3,w.z,acc[3][2]); acc[3][3]=fmaf(x3,w.w,acc[3][3]);
    }
    #pragma unroll
    for (int i = 0; i < 4; i++){
        float4 v = make_float4(acc[i][0],acc[i][1],acc[i][2],acc[i][3]);
        *(float4*)&g_Y[(rowbase + r0 + i)*32 + c0] = v;
    }
}

// Z[dst] += Y[src], width 32, vector-4 reductions
__global__ void k_scatter32(const int* __restrict__ ei){
    int idx = blockIdx.x*blockDim.x + threadIdx.x;
    if (idx >= NE*8) return;
    int e = idx >> 3, q = idx & 7;
    int src = __ldg(&ei[e]);
    int dst = __ldg(&ei[NE + e]);
    float4 v = reinterpret_cast<const float4*>(g_Y)[src*8 + q];
    red_add_v4(&g_Z[dst*32 + q*4], v);
}

// feat[:, out_off:out_off+32] = tanh((Z + Y + b) / deg)
__global__ void k_finish32(const float* __restrict__ bias, int out_off){
    int idx = blockIdx.x*blockDim.x + threadIdx.x;
    if (idx >= NN*32) return;
    int n = idx >> 5, f = idx & 31;
    float v = (g_Z[idx] + g_Y[idx] + bias[f]) / g_deg[n];
    g_feat[n*DLAT + out_off + f] = tanhf(v);
}

// Y1[n] = h2[n,:] @ W3   (32 -> 1), warp per row
__global__ void k_matvec(const float* __restrict__ W3){
    int tid = threadIdx.x;
    int lane = tid & 31, warp = tid >> 5;
    int row = blockIdx.x*8 + warp;
    float v = g_feat[row*DLAT + 64 + lane] * W3[lane];
    #pragma unroll
    for (int s = 16; s > 0; s >>= 1) v += __shfl_xor_sync(0xffffffffu, v, s);
    if (lane == 0) g_Y[row] = v;
}

__global__ void k_scatter1(const int* __restrict__ ei){
    int e = blockIdx.x*blockDim.x + threadIdx.x;
    if (e >= NE) return;
    atomicAdd(&g_Z[__ldg(&ei[NE+e])], g_Y[__ldg(&ei[e])]);
}

__global__ void k_finish1(const float* __restrict__ b3){
    int n = blockIdx.x*blockDim.x + threadIdx.x;
    if (n >= NN) return;
    g_feat[n*DLAT + 96] = tanhf((g_Z[n] + g_Y[n] + b3[0]) / g_deg[n]);
}

// one block per graph: bitonic top-k sort, gather, conv1+pool+conv2+dense
__global__ void k_head(const float* __restrict__ wc1, const float* __restrict__ bc1,
                       const float* __restrict__ wc2, const float* __restrict__ bc2,
                       const float* __restrict__ wout, const float* __restrict__ bout,
                       float* __restrict__ out){
    __shared__ float s_val[NPG];
    __shared__ int   s_idx[NPG];
    __shared__ float s_sp[KTOP*DLAT];
    __shared__ float s_w1[C1*DLAT];
    __shared__ float s_t1[C1*30];
    __shared__ float s_p[C1*15];
    __shared__ float s_q[C2*11];
    int b = blockIdx.x, tid = threadIdx.x;
    for (int i = tid; i < NPG; i += blockDim.x){
        s_val[i] = g_feat[(b*NPG + i)*DLAT + 96];
        s_idx[i] = i;
    }
    for (int i = tid; i < C1*DLAT; i += blockDim.x) s_w1[i] = wc1[i];
    __syncthreads();
    // bitonic sort: descending by val, ties -> ascending index (lax.top_k semantics)
    for (int k = 2; k <= NPG; k <<= 1){
        for (int j = k >> 1; j > 0; j >>= 1){
            for (int i = tid; i < NPG; i += blockDim.x){
                int ixj = i ^ j;
                if (ixj > i){
                    float va = s_val[i], vb = s_val[ixj];
                    int ia = s_idx[i], ib = s_idx[ixj];
                    bool before_ba = (vb > va) || (vb == va && ib < ia);
                    bool up = ((i & k) == 0);
                    if (up ? before_ba : !before_ba){
                        s_val[i] = vb; s_val[ixj] = va;
                        s_idx[i] = ib; s_idx[ixj] = ia;
                    }
                }
            }
            __syncthreads();
        }
    }
    // gather top-30 feature rows
    for (int t = tid; t < KTOP*DLAT; t += blockDim.x){
        int kk = t / DLAT, d = t % DLAT;
        int node = b*NPG + s_idx[kk];
        s_sp[t] = g_feat[node*DLAT + d];
    }
    __syncthreads();
    // conv1 (kernel=stride=97 -> per-node dot) + relu -> [16][30]
    for (int t = tid; t < C1*30; t += blockDim.x){
        int c = t / 30, j = t % 30;
        float acc = bc1[c];
        for (int d = 0; d < DLAT; d++) acc = fmaf(s_sp[j*DLAT + d], s_w1[c*DLAT + d], acc);
        s_t1[t] = fmaxf(acc, 0.f);
    }
    __syncthreads();
    // maxpool(2,2) -> [16][15]
    for (int t = tid; t < C1*15; t += blockDim.x){
        int c = t / 15, l = t % 15;
        s_p[t] = fmaxf(s_t1[c*30 + 2*l], s_t1[c*30 + 2*l + 1]);
    }
    __syncthreads();
    // conv2 (16->32, k=5) + relu -> [32][11]
    for (int t = tid; t < C2*11; t += blockDim.x){
        int c2 = t / 11, l = t % 11;
        float acc = bc2[c2];
        for (int c1 = 0; c1 < C1; c1++)
            #pragma unroll
            for (int tt = 0; tt < KW2; tt++)
                acc = fmaf(s_p[c1*15 + l + tt], wc2[(c2*C1 + c1)*KW2 + tt], acc);
        s_q[t] = fmaxf(acc, 0.f);
    }
    __syncthreads();
    // dense [352 -> 2] + relu
    if (tid < 64){
        int o = tid >> 5, lane = tid & 31;
        float acc = 0.f;
        for (int i = lane; i < C2*11; i += 32) acc = fmaf(s_q[i], wout[i*OUTC + o], acc);
        #pragma unroll
        for (int s = 16; s > 0; s >>= 1) acc += __shfl_xor_sync(0xffffffffu, acc, s);
        if (lane == 0) out[b*OUTC + o] = fmaxf(acc + bout[o], 0.f);
    }
}

extern "C" void kernel_launch(void* const* d_in, const int* in_sizes, int n_in,
                              void* d_out, int out_size){
    const float* nf   = (const float*)d_in[0];
    const float* ef   = (const float*)d_in[1];
    const int*   ei   = (const int*)  d_in[2];
    const float* W0   = (const float*)d_in[3];
    const float* b0   = (const float*)d_in[4];
    const float* W1   = (const float*)d_in[5];
    const float* b1   = (const float*)d_in[6];
    const float* W2   = (const float*)d_in[7];
    const float* b2   = (const float*)d_in[8];
    const float* W3   = (const float*)d_in[9];
    const float* b3   = (const float*)d_in[10];
    const float* wc1  = (const float*)d_in[11];
    const float* bc1  = (const float*)d_in[12];
    const float* wc2  = (const float*)d_in[13];
    const float* bc2  = (const float*)d_in[14];
    const float* wout = (const float*)d_in[15];
    const float* bout = (const float*)d_in[16];
    float* out = (float*)d_out;

    const int T = 256;
    k_init<<<(NN*32 + T-1)/T, T>>>();
    k_edge<<<(NE*8 + T-1)/T, T>>>(ef, ei);
    // hop 0: 160 -> 32
    k_zero<<<(NN*32 + T-1)/T, T>>>(NN*32);
    k_gemm0<<<NN/128, 256>>>(nf, W0);
    k_scatter32<<<(NE*8 + T-1)/T, T>>>(ei);
    k_finish32<<<(NN*32 + T-1)/T, T>>>(b0, 0);
    // hop 1: 32 -> 32
    k_zero<<<(NN*32 + T-1)/T, T>>>(NN*32);
    k_gemm32<<<NN/128, 256>>>(W1, 0);
    k_scatter32<<<(NE*8 + T-1)/T, T>>>(ei);
    k_finish32<<<(NN*32 + T-1)/T, T>>>(b1, 32);
    // hop 2: 32 -> 32
    k_zero<<<(NN*32 + T-1)/T, T>>>(NN*32);
    k_gemm32<<<NN/128, 256>>>(W2, 32);
    k_scatter32<<<(NE*8 + T-1)/T, T>>>(ei);
    k_finish32<<<(NN*32 + T-1)/T, T>>>(b2, 64);
    // hop 3: 32 -> 1
    k_zero<<<(NN + T-1)/T, T>>>(NN);
    k_matvec<<<NN/8, 256>>>(W3);
    k_scatter1<<<(NE + T-1)/T, T>>>(ei);
    k_finish1<<<(NN + T-1)/T, T>>>(b3);
    // sort-pool + conv head
    k_head<<<NB, 1024>>>(wc1, bc1, wc2, bc2, wout, bout, out);
}

// round 3
// speedup vs baseline: 1.8455x; 1.2690x over previous
#include <cuda_runtime.h>
#include <cstdint>

#define NB   128
#define NPG  1024
#define NN   (NB*NPG)      // 131072 nodes
#define NE   (NN*8)        // 1048576 edges
#define DLAT 97
#define KTOP 30
#define C1   16
#define C2   32
#define KW2  5
#define OUTC 2

// scratch (device globals — no allocation allowed)
__device__ float g_deg[NN];
__device__ float g_e2n[NN*32];      // edge pool for hop0; reused as width-1 accumulator for hop3
__device__ float g_feat[NN*DLAT];   // concat(h0,h1,h2,h3) row-major [N][97]
__device__ float g_Y[NN*32];
__device__ float g_Z[NN*32];

__device__ __forceinline__ void red_add_v4(float* addr, float4 v){
    asm volatile("red.global.add.v4.f32 [%0], {%1,%2,%3,%4};"
        :: "l"(addr), "f"(v.x), "f"(v.y), "f"(v.z), "f"(v.w) : "memory");
}

__global__ void k_init(){
    int idx = blockIdx.x*blockDim.x + threadIdx.x;
    if (idx < NN) g_deg[idx] = 1.0f;
    if (idx < NN*32) g_e2n[idx] = 0.0f;
}

// e2n = segment_sum(edge_feat, dst); deg = 1 + indegree
__global__ void k_edge(const float* __restrict__ ef, const int* __restrict__ ei){
    int idx = blockIdx.x*blockDim.x + threadIdx.x;
    if (idx >= NE*8) return;
    int e = idx >> 3, q = idx & 7;
    int dst = __ldg(&ei[NE + e]);
    float4 v = reinterpret_cast<const float4*>(ef)[idx];
    red_add_v4(&g_e2n[dst*32 + q*4], v);
    if (q == 0) atomicAdd(&g_deg[dst], 1.0f);
}

// ---------------------------------------------------------------------------
// hop 0 GEMM: Y = [node_feat(128) | e2n(32)] @ W0  (K=160, N=32)
// 128-row block tile, 256 threads, 4x4 thread tile, cp.async double buffering.
// Writes Y and Z (Z pre-loaded with self term).
// ---------------------------------------------------------------------------
#define G0_SW   (160*32)               // 5120 floats
#define G0_XSTR 36                     // padded row stride (16B aligned)
#define G0_XBUF (128*G0_XSTR)          // one X buffer
#define G0_SMEM ((G0_SW + 2*G0_XBUF)*4)  // 57344 bytes

__global__ __launch_bounds__(256) void k_gemm0(const float* __restrict__ nf,
                                               const float* __restrict__ W){
    extern __shared__ float sm[];
    float* sW = sm;                    // [160*32]
    float* sX = sm + G0_SW;            // [2][128][36]
    int tid = threadIdx.x;
    int rowbase = blockIdx.x*128;
    for (int i = tid; i < G0_SW; i += 256) sW[i] = W[i];

    // async chunk loader: 128 rows x 32 cols = 1024 float4s, 4 per thread
    auto load_chunk = [&](int kc, int buf){
        #pragma unroll
        for (int i = 0; i < 4; i++){
            int t = tid + i*256;
            int r = t >> 3, q = t & 7;
            const float* src = (kc < 128)
                ? &nf[(size_t)(rowbase + r)*128 + kc + q*4]
                : &g_e2n[(size_t)(rowbase + r)*32 + q*4];
            uint32_t sa = (uint32_t)__cvta_generic_to_shared(&sX[buf*G0_XBUF + r*G0_XSTR + q*4]);
            asm volatile("cp.async.ca.shared.global [%0], [%1], 16;" :: "r"(sa), "l"(src) : "memory");
        }
        asm volatile("cp.async.commit_group;" ::: "memory");
    };

    load_chunk(0, 0);
    int c0 = (tid & 7)*4, r0 = (tid >> 3)*4;
    float acc[4][4];
    #pragma unroll
    for (int i=0;i<4;i++)
        #pragma unroll
        for (int j=0;j<4;j++) acc[i][j]=0.f;

    #pragma unroll
    for (int c = 0; c < 5; c++){
        if (c < 4) load_chunk((c+1)*32, (c+1)&1);
        if (c < 4) asm volatile("cp.async.wait_group 1;" ::: "memory");
        else       asm volatile("cp.async.wait_group 0;" ::: "memory");
        __syncthreads();
        const float* xb = &sX[(c&1)*G0_XBUF];
        #pragma unroll
        for (int k = 0; k < 32; k++){
            float4 w = *(const float4*)&sW[(c*32+k)*32 + c0];
            float x0=xb[(r0  )*G0_XSTR+k], x1=xb[(r0+1)*G0_XSTR+k];
            float x2=xb[(r0+2)*G0_XSTR+k], x3=xb[(r0+3)*G0_XSTR+k];
            acc[0][0]=fmaf(x0,w.x,acc[0][0]); acc[0][1]=fmaf(x0,w.y,acc[0][1]);
            acc[0][2]=fmaf(x0,w.z,acc[0][2]); acc[0][3]=fmaf(x0,w.w,acc[0][3]);
            acc[1][0]=fmaf(x1,w.x,acc[1][0]); acc[1][1]=fmaf(x1,w.y,acc[1][1]);
            acc[1][2]=fmaf(x1,w.z,acc[1][2]); acc[1][3]=fmaf(x1,w.w,acc[1][3]);
            acc[2][0]=fmaf(x2,w.x,acc[2][0]); acc[2][1]=fmaf(x2,w.y,acc[2][1]);
            acc[2][2]=fmaf(x2,w.z,acc[2][2]); acc[2][3]=fmaf(x2,w.w,acc[2][3]);
            acc[3][0]=fmaf(x3,w.x,acc[3][0]); acc[3][1]=fmaf(x3,w.y,acc[3][1]);
            acc[3][2]=fmaf(x3,w.z,acc[3][2]); acc[3][3]=fmaf(x3,w.w,acc[3][3]);
        }
        __syncthreads();
    }
    #pragma unroll
    for (int i = 0; i < 4; i++){
        float4 v = make_float4(acc[i][0],acc[i][1],acc[i][2],acc[i][3]);
        size_t off = (size_t)(rowbase + r0 + i)*32 + c0;
        *(float4*)&g_Y[off] = v;
        *(float4*)&g_Z[off] = v;     // self-loop init for scatter
    }
}

// Z[dst] += Y[src], width 32, vector-4 reductions
__global__ void k_scatter32(const int* __restrict__ ei){
    int idx = blockIdx.x*blockDim.x + threadIdx.x;
    if (idx >= NE*8) return;
    int e = idx >> 3, q = idx & 7;
    int src = __ldg(&ei[e]);
    int dst = __ldg(&ei[NE + e]);
    float4 v = reinterpret_cast<const float4*>(g_Y)[src*8 + q];
    red_add_v4(&g_Z[dst*32 + q*4], v);
}

// ---------------------------------------------------------------------------
// Fused: h_i = tanh((Z + b)/deg) -> g_feat[:, feat_off], then Y = h_i @ W
// (writes Y and Z = Y for the next hop's scatter)
// ---------------------------------------------------------------------------
__global__ __launch_bounds__(256) void k_gemm_h(const float* __restrict__ W,
                                                const float* __restrict__ bias,
                                                int feat_off){
    __shared__ float sX[128][33];
    __shared__ float sW[32*32];
    __shared__ float sB[32];
    int tid = threadIdx.x;
    int rowbase = blockIdx.x*128;
    for (int i = tid; i < 32*32; i += 256) sW[i] = W[i];
    if (tid < 32) sB[tid] = bias[tid];
    // fused finish of previous hop: tanh((Z+b)/deg), store to feat + smem
    for (int i = tid; i < 128*32; i += 256){
        int r = i >> 5, k = i & 31;
        int n = rowbase + r;
        float h = tanhf((g_Z[(size_t)n*32 + k] + __ldg(&bias[k])) / g_deg[n]);
        sX[r][k] = h;
        g_feat[(size_t)n*DLAT + feat_off + k] = h;
    }
    int c0 = (tid & 7)*4, r0 = (tid >> 3)*4;
    float acc[4][4];
    #pragma unroll
    for (int i=0;i<4;i++)
        #pragma unroll
        for (int j=0;j<4;j++) acc[i][j]=0.f;
    __syncthreads();
    #pragma unroll
    for (int k = 0; k < 32; k++){
        float4 w = *(const float4*)&sW[k*32 + c0];
        float x0=sX[r0][k], x1=sX[r0+1][k], x2=sX[r0+2][k], x3=sX[r0+3][k];
        acc[0][0]=fmaf(x0,w.x,acc[0][0]); acc[0][1]=fmaf(x0,w.y,acc[0][1]);
        acc[0][2]=fmaf(x0,w.z,acc[0][2]); acc[0][3]=fmaf(x0,w.w,acc[0][3]);
        acc[1][0]=fmaf(x1,w.x,acc[1][0]); acc[1][1]=fmaf(x1,w.y,acc[1][1]);
        acc[1][2]=fmaf(x1,w.z,acc[1][2]); acc[1][3]=fmaf(x1,w.w,acc[1][3]);
        acc[2][0]=fmaf(x2,w.x,acc[2][0]); acc[2][1]=fmaf(x2,w.y,acc[2][1]);
        acc[2][2]=fmaf(x2,w.z,acc[2][2]); acc[2][3]=fmaf(x2,w.w,acc[2][3]);
        acc[3][0]=fmaf(x3,w.x,acc[3][0]); acc[3][1]=fmaf(x3,w.y,acc[3][1]);
        acc[3][2]=fmaf(x3,w.z,acc[3][2]); acc[3][3]=fmaf(x3,w.w,acc[3][3]);
    }
    #pragma unroll
    for (int i = 0; i < 4; i++){
        float4 v = make_float4(acc[i][0],acc[i][1],acc[i][2],acc[i][3]);
        size_t off = (size_t)(rowbase + r0 + i)*32 + c0;
        *(float4*)&g_Y[off] = v;
        *(float4*)&g_Z[off] = v;
    }
}

// ---------------------------------------------------------------------------
// Fused: h2 = tanh((Z + b2)/deg) -> feat[:,64..95]; y = h2 @ W3 (scalar).
// Writes g_Y[row] = y and g_e2n[row] = y (hop-3 accumulator init; e2n is dead).
// ---------------------------------------------------------------------------
__global__ void k_matvec(const float* __restrict__ W3, const float* __restrict__ b2){
    int tid = threadIdx.x;
    int lane = tid & 31, warp = tid >> 5;
    int row = blockIdx.x*8 + warp;
    float h = tanhf((g_Z[(size_t)row*32 + lane] + __ldg(&b2[lane])) / g_deg[row]);
    g_feat[(size_t)row*DLAT + 64 + lane] = h;
    float v = h * __ldg(&W3[lane]);
    #pragma unroll
    for (int s = 16; s > 0; s >>= 1) v += __shfl_xor_sync(0xffffffffu, v, s);
    if (lane == 0){ g_Y[row] = v; g_e2n[row] = v; }
}

// hop-3 scatter into g_e2n (width 1)
__global__ void k_scatter1(const int* __restrict__ ei){
    int e = blockIdx.x*blockDim.x + threadIdx.x;
    if (e >= NE) return;
    atomicAdd(&g_e2n[__ldg(&ei[NE+e])], g_Y[__ldg(&ei[e])]);
}

// ---------------------------------------------------------------------------
// one block per graph: fused finish of hop3, bitonic top-k sort, gather,
// conv1+pool+conv2+dense
// ---------------------------------------------------------------------------
__global__ void k_head(const float* __restrict__ b3,
                       const float* __restrict__ wc1, const float* __restrict__ bc1,
                       const float* __restrict__ wc2, const float* __restrict__ bc2,
                       const float* __restrict__ wout, const float* __restrict__ bout,
                       float* __restrict__ out){
    __shared__ float s_val[NPG];
    __shared__ int   s_idx[NPG];
    __shared__ float s_sp[KTOP*DLAT];
    __shared__ float s_w1[C1*DLAT];
    __shared__ float s_t1[C1*30];
    __shared__ float s_p[C1*15];
    __shared__ float s_q[C2*11];
    int b = blockIdx.x, tid = threadIdx.x;
    float bias3 = __ldg(&b3[0]);
    for (int i = tid; i < NPG; i += blockDim.x){
        int node = b*NPG + i;
        float h = tanhf((g_e2n[node] + bias3) / g_deg[node]);
        g_feat[(size_t)node*DLAT + 96] = h;
        s_val[i] = h;
        s_idx[i] = i;
    }
    for (int i = tid; i < C1*DLAT; i += blockDim.x) s_w1[i] = wc1[i];
    __syncthreads();
    // bitonic sort: descending by val, ties -> ascending index (lax.top_k semantics)
    for (int k = 2; k <= NPG; k <<= 1){
        for (int j = k >> 1; j > 0; j >>= 1){
            for (int i = tid; i < NPG; i += blockDim.x){
                int ixj = i ^ j;
                if (ixj > i){
                    float va = s_val[i], vb = s_val[ixj];
                    int ia = s_idx[i], ib = s_idx[ixj];
                    bool before_ba = (vb > va) || (vb == va && ib < ia);
                    bool up = ((i & k) == 0);
                    if (up ? before_ba : !before_ba){
                        s_val[i] = vb; s_val[ixj] = va;
                        s_idx[i] = ib; s_idx[ixj] = ia;
                    }
                }
            }
            __syncthreads();
        }
    }
    // gather top-30 feature rows
    for (int t = tid; t < KTOP*DLAT; t += blockDim.x){
        int kk = t / DLAT, d = t % DLAT;
        int node = b*NPG + s_idx[kk];
        s_sp[t] = g_feat[(size_t)node*DLAT + d];
    }
    __syncthreads();
    // conv1 (kernel=stride=97 -> per-node dot) + relu -> [16][30]
    for (int t = tid; t < C1*30; t += blockDim.x){
        int c = t / 30, j = t % 30;
        float acc = bc1[c];
        for (int d = 0; d < DLAT; d++) acc = fmaf(s_sp[j*DLAT + d], s_w1[c*DLAT + d], acc);
        s_t1[t] = fmaxf(acc, 0.f);
    }
    __syncthreads();
    // maxpool(2,2) -> [16][15]
    for (int t = tid; t < C1*15; t += blockDim.x){
        int c = t / 15, l = t % 15;
        s_p[t] = fmaxf(s_t1[c*30 + 2*l], s_t1[c*30 + 2*l + 1]);
    }
    __syncthreads();
    // conv2 (16->32, k=5) + relu -> [32][11]
    for (int t = tid; t < C2*11; t += blockDim.x){
        int c2 = t / 11, l = t % 11;
        float acc = bc2[c2];
        for (int c1 = 0; c1 < C1; c1++)
            #pragma unroll
            for (int tt = 0; tt < KW2; tt++)
                acc = fmaf(s_p[c1*15 + l + tt], wc2[(c2*C1 + c1)*KW2 + tt], acc);
        s_q[t] = fmaxf(acc, 0.f);
    }
    __syncthreads();
    // dense [352 -> 2] + relu
    if (tid < 64){
        int o = tid >> 5, lane = tid & 31;
        float acc = 0.f;
        for (int i = lane; i < C2*11; i += 32) acc = fmaf(s_q[i], wout[i*OUTC + o], acc);
        #pragma unroll
        for (int s = 16; s > 0; s >>= 1) acc += __shfl_xor_sync(0xffffffffu, acc, s);
        if (lane == 0) out[b*OUTC + o] = fmaxf(acc + bout[o], 0.f);
    }
}

extern "C" void kernel_launch(void* const* d_in, const int* in_sizes, int n_in,
                              void* d_out, int out_size){
    const float* nf   = (const float*)d_in[0];
    const float* ef   = (const float*)d_in[1];
    const int*   ei   = (const int*)  d_in[2];
    const float* W0   = (const float*)d_in[3];
    const float* b0   = (const float*)d_in[4];
    const float* W1   = (const float*)d_in[5];
    const float* b1   = (const float*)d_in[6];
    const float* W2   = (const float*)d_in[7];
    const float* b2   = (const float*)d_in[8];
    const float* W3   = (const float*)d_in[9];
    const float* b3   = (const float*)d_in[10];
    const float* wc1  = (const float*)d_in[11];
    const float* bc1  = (const float*)d_in[12];
    const float* wc2  = (const float*)d_in[13];
    const float* bc2  = (const float*)d_in[14];
    const float* wout = (const float*)d_in[15];
    const float* bout = (const float*)d_in[16];
    float* out = (float*)d_out;

    static int configured = 0;
    if (!configured){
        cudaFuncSetAttribute(k_gemm0, cudaFuncAttributeMaxDynamicSharedMemorySize, G0_SMEM);
        configured = 1;
    }

    const int T = 256;
    k_init<<<(NN*32 + T-1)/T, T>>>();
    k_edge<<<(NE*8 + T-1)/T, T>>>(ef, ei);
    // hop 0: 160 -> 32 (Y, Z=Y)
    k_gemm0<<<NN/128, 256, G0_SMEM>>>(nf, W0);
    k_scatter32<<<(NE*8 + T-1)/T, T>>>(ei);
    // hop 1: finish hop0 + 32 -> 32
    k_gemm_h<<<NN/128, 256>>>(W1, b0, 0);
    k_scatter32<<<(NE*8 + T-1)/T, T>>>(ei);
    // hop 2: finish hop1 + 32 -> 32
    k_gemm_h<<<NN/128, 256>>>(W2, b1, 32);
    k_scatter32<<<(NE*8 + T-1)/T, T>>>(ei);
    // hop 3: finish hop2 + 32 -> 1
    k_matvec<<<NN/8, 256>>>(W3, b2);
    k_scatter1<<<(NE + T-1)/T, T>>>(ei);
    // finish hop3 + sort-pool + conv head
    k_head<<<NB, 1024>>>(b3, wc1, bc1, wc2, bc2, wout, bout, out);
}

// round 4
// speedup vs baseline: 1.9062x; 1.0329x over previous
#include <cuda_runtime.h>
#include <cstdint>

#define NB   128
#define NPG  1024
#define NN   (NB*NPG)      // 131072 nodes
#define NE   (NN*8)        // 1048576 edges
#define DLAT 97
#define KTOP 30
#define C1   16
#define C2   32
#define KW2  5
#define OUTC 2

// scratch (device globals — no allocation allowed)
__device__ float g_e2n[NN*32];
__device__ float g_feat[NN*DLAT];   // concat(h0,h1,h2,h3) row-major [N][97]
__device__ float g_Y[NN*32];
__device__ float g_Z[NN*32];        // ping-pong buffer; reused width-1 for hop3
__device__ int   g_cnt[NN];
__device__ int   g_rowptr[NN+1];
__device__ int   g_cursor[NN];
__device__ int   g_csr[NE];
__device__ int   g_bsum[128];

__device__ __forceinline__ void red_add_v4(float* addr, float4 v){
    asm volatile("red.global.add.v4.f32 [%0], {%1,%2,%3,%4};"
        :: "l"(addr), "f"(v.x), "f"(v.y), "f"(v.z), "f"(v.w) : "memory");
}

__global__ void k_init(){
    int idx = blockIdx.x*blockDim.x + threadIdx.x;
    if (idx < NN) g_cnt[idx] = 0;
    if (idx < NN*32) g_e2n[idx] = 0.0f;
}

// e2n = segment_sum(edge_feat, dst); cnt = indegree
__global__ void k_edge(const float* __restrict__ ef, const int* __restrict__ ei){
    int idx = blockIdx.x*blockDim.x + threadIdx.x;
    if (idx >= NE*8) return;
    int e = idx >> 3, q = idx & 7;
    int dst = __ldg(&ei[NE + e]);
    float4 v = reinterpret_cast<const float4*>(ef)[idx];
    red_add_v4(&g_e2n[dst*32 + q*4], v);
    if (q == 0) atomicAdd(&g_cnt[dst], 1);
}

// block-level exclusive scan of cnt (128 blocks x 1024)
__global__ __launch_bounds__(1024) void k_scan1(){
    __shared__ int s[1024];
    int tid = threadIdx.x;
    int i = blockIdx.x*1024 + tid;
    int v = g_cnt[i];
    s[tid] = v; __syncthreads();
    #pragma unroll
    for (int d = 1; d < 1024; d <<= 1){
        int t = (tid >= d) ? s[tid-d] : 0;
        __syncthreads();
        s[tid] += t;
        __syncthreads();
    }
    g_rowptr[i] = s[tid] - v;
    if (tid == 1023) g_bsum[blockIdx.x] = s[tid];
}

// add block offsets; fill cursor
__global__ __launch_bounds__(1024) void k_scan2(){
    __shared__ int bs[128];
    int tid = threadIdx.x;
    if (tid == 0){
        int r = 0;
        for (int i = 0; i < 128; i++){ int t = g_bsum[i]; bs[i] = r; r += t; }
    }
    __syncthreads();
    for (int i = tid; i < NN; i += 1024){
        int r = g_rowptr[i] + bs[i >> 10];
        g_rowptr[i] = r;
        g_cursor[i] = r;
    }
    if (tid == 0) g_rowptr[NN] = NE;
}

// bin: csr[pos] = src, grouped by dst
__global__ void k_bin(const int* __restrict__ ei){
    int e = blockIdx.x*blockDim.x + threadIdx.x;
    if (e >= NE) return;
    int src = __ldg(&ei[e]);
    int dst = __ldg(&ei[NE + e]);
    int pos = atomicAdd(&g_cursor[dst], 1);
    g_csr[pos] = src;
}

// ---------------------------------------------------------------------------
// hop 0 GEMM: Y = [node_feat(128) | e2n(32)] @ W0  (K=160, N=32)
// ---------------------------------------------------------------------------
#define G0_SW   (160*32)
#define G0_XSTR 36
#define G0_XBUF (128*G0_XSTR)
#define G0_SMEM ((G0_SW + 2*G0_XBUF)*4)  // 57344 bytes

__global__ __launch_bounds__(256) void k_gemm0(const float* __restrict__ nf,
                                               const float* __restrict__ W){
    extern __shared__ float sm[];
    float* sW = sm;
    float* sX = sm + G0_SW;
    int tid = threadIdx.x;
    int rowbase = blockIdx.x*128;
    for (int i = tid; i < G0_SW; i += 256) sW[i] = W[i];

    auto load_chunk = [&](int kc, int buf){
        #pragma unroll
        for (int i = 0; i < 4; i++){
            int t = tid + i*256;
            int r = t >> 3, q = t & 7;
            const float* src = (kc < 128)
                ? &nf[(size_t)(rowbase + r)*128 + kc + q*4]
                : &g_e2n[(size_t)(rowbase + r)*32 + q*4];
            uint32_t sa = (uint32_t)__cvta_generic_to_shared(&sX[buf*G0_XBUF + r*G0_XSTR + q*4]);
            asm volatile("cp.async.ca.shared.global [%0], [%1], 16;" :: "r"(sa), "l"(src) : "memory");
        }
        asm volatile("cp.async.commit_group;" ::: "memory");
    };

    load_chunk(0, 0);
    int c0 = (tid & 7)*4, r0 = (tid >> 3)*4;
    float acc[4][4];
    #pragma unroll
    for (int i=0;i<4;i++)
        #pragma unroll
        for (int j=0;j<4;j++) acc[i][j]=0.f;

    #pragma unroll
    for (int c = 0; c < 5; c++){
        if (c < 4) load_chunk((c+1)*32, (c+1)&1);
        if (c < 4) asm volatile("cp.async.wait_group 1;" ::: "memory");
        else       asm volatile("cp.async.wait_group 0;" ::: "memory");
        __syncthreads();
        const float* xb = &sX[(c&1)*G0_XBUF];
        #pragma unroll
        for (int k = 0; k < 32; k++){
            float4 w = *(const float4*)&sW[(c*32+k)*32 + c0];
            float x0=xb[(r0  )*G0_XSTR+k], x1=xb[(r0+1)*G0_XSTR+k];
            float x2=xb[(r0+2)*G0_XSTR+k], x3=xb[(r0+3)*G0_XSTR+k];
            acc[0][0]=fmaf(x0,w.x,acc[0][0]); acc[0][1]=fmaf(x0,w.y,acc[0][1]);
            acc[0][2]=fmaf(x0,w.z,acc[0][2]); acc[0][3]=fmaf(x0,w.w,acc[0][3]);
            acc[1][0]=fmaf(x1,w.x,acc[1][0]); acc[1][1]=fmaf(x1,w.y,acc[1][1]);
            acc[1][2]=fmaf(x1,w.z,acc[1][2]); acc[1][3]=fmaf(x1,w.w,acc[1][3]);
            acc[2][0]=fmaf(x2,w.x,acc[2][0]); acc[2][1]=fmaf(x2,w.y,acc[2][1]);
            acc[2][2]=fmaf(x2,w.z,acc[2][2]); acc[2][3]=fmaf(x2,w.w,acc[2][3]);
            acc[3][0]=fmaf(x3,w.x,acc[3][0]); acc[3][1]=fmaf(x3,w.y,acc[3][1]);
            acc[3][2]=fmaf(x3,w.z,acc[3][2]); acc[3][3]=fmaf(x3,w.w,acc[3][3]);
        }
        __syncthreads();
    }
    #pragma unroll
    for (int i = 0; i < 4; i++){
        float4 v = make_float4(acc[i][0],acc[i][1],acc[i][2],acc[i][3]);
        *(float4*)&g_Y[(size_t)(rowbase + r0 + i)*32 + c0] = v;
    }
}

// ---------------------------------------------------------------------------
// Fused hop: aggregate prev Y over CSR (+self), tanh((.+b)/deg) -> feat,
// then 32x32 GEMM -> next Y.  dir=0: Yin=g_Y, Yout=g_Z ; dir=1: swapped.
// 256 threads = 32 nodes x 8 feature-quads.
// ---------------------------------------------------------------------------
__global__ __launch_bounds__(256) void k_hop(const float* __restrict__ W,
                                             const float* __restrict__ bias,
                                             int feat_off, int dir){
    const float* Yin  = dir ? g_Z : g_Y;
    float*       Yout = dir ? g_Y : g_Z;
    __shared__ float sX[32][33];
    __shared__ float sW[32*32];
    __shared__ int   sRP[33];
    int tid = threadIdx.x;
    int base = blockIdx.x*32;
    for (int i = tid; i < 32*32; i += 256) sW[i] = W[i];
    if (tid < 33) sRP[tid] = g_rowptr[base + tid];
    __syncthreads();

    int nl = tid >> 3, q = tid & 7;
    int node = base + nl;
    int s = sRP[nl], e = sRP[nl+1];
    float4 acc = *(const float4*)&Yin[(size_t)node*32 + q*4];
    for (int j = s; j < e; j++){
        int src = __ldg(&g_csr[j]);
        float4 v = *(const float4*)&Yin[(size_t)src*32 + q*4];
        acc.x += v.x; acc.y += v.y; acc.z += v.z; acc.w += v.w;
    }
    float invdeg = 1.0f / (float)(e - s + 1);
    float h0 = tanhf((acc.x + __ldg(&bias[q*4+0])) * invdeg);
    float h1 = tanhf((acc.y + __ldg(&bias[q*4+1])) * invdeg);
    float h2 = tanhf((acc.z + __ldg(&bias[q*4+2])) * invdeg);
    float h3 = tanhf((acc.w + __ldg(&bias[q*4+3])) * invdeg);
    sX[nl][q*4+0] = h0; sX[nl][q*4+1] = h1;
    sX[nl][q*4+2] = h2; sX[nl][q*4+3] = h3;
    float* fp = &g_feat[(size_t)node*DLAT + feat_off + q*4];
    fp[0] = h0; fp[1] = h1; fp[2] = h2; fp[3] = h3;
    __syncthreads();

    // GEMM 32x32x32: thread = (row r, 4 cols)
    int r = tid >> 3, c0 = (tid & 7)*4;
    float a0=0.f, a1=0.f, a2=0.f, a3=0.f;
    #pragma unroll
    for (int k = 0; k < 32; k++){
        float x = sX[r][k];
        float4 w = *(const float4*)&sW[k*32 + c0];
        a0 = fmaf(x, w.x, a0); a1 = fmaf(x, w.y, a1);
        a2 = fmaf(x, w.z, a2); a3 = fmaf(x, w.w, a3);
    }
    *(float4*)&Yout[(size_t)(base + r)*32 + c0] = make_float4(a0,a1,a2,a3);
}

// ---------------------------------------------------------------------------
// Fused hop3: aggregate g_Y (h2 pre-acts), tanh -> feat[:,64..95],
// then matvec W3 -> g_Z[node] (width-1).
// ---------------------------------------------------------------------------
__global__ __launch_bounds__(256) void k_hopC(const float* __restrict__ W3,
                                              const float* __restrict__ b2){
    __shared__ float sX[32][33];
    __shared__ float sW3[32];
    __shared__ int   sRP[33];
    int tid = threadIdx.x;
    int base = blockIdx.x*32;
    if (tid < 32) sW3[tid] = W3[tid];
    if (tid < 33) sRP[tid] = g_rowptr[base + tid];
    __syncthreads();

    int nl = tid >> 3, q = tid & 7;
    int node = base + nl;
    int s = sRP[nl], e = sRP[nl+1];
    float4 acc = *(const float4*)&g_Y[(size_t)node*32 + q*4];
    for (int j = s; j < e; j++){
        int src = __ldg(&g_csr[j]);
        float4 v = *(const float4*)&g_Y[(size_t)src*32 + q*4];
        acc.x += v.x; acc.y += v.y; acc.z += v.z; acc.w += v.w;
    }
    float invdeg = 1.0f / (float)(e - s + 1);
    float h0 = tanhf((acc.x + __ldg(&b2[q*4+0])) * invdeg);
    float h1 = tanhf((acc.y + __ldg(&b2[q*4+1])) * invdeg);
    float h2 = tanhf((acc.z + __ldg(&b2[q*4+2])) * invdeg);
    float h3 = tanhf((acc.w + __ldg(&b2[q*4+3])) * invdeg);
    sX[nl][q*4+0] = h0; sX[nl][q*4+1] = h1;
    sX[nl][q*4+2] = h2; sX[nl][q*4+3] = h3;
    float* fp = &g_feat[(size_t)node*DLAT + 64 + q*4];
    fp[0] = h0; fp[1] = h1; fp[2] = h2; fp[3] = h3;
    __syncthreads();

    if (tid < 32){
        float a = 0.f;
        #pragma unroll
        for (int k = 0; k < 32; k++) a = fmaf(sX[tid][k], sW3[k], a);
        g_Z[base + tid] = a;   // width-1 pre-activation for hop 3
    }
}

// ---------------------------------------------------------------------------
// one block per graph: fused hop3 aggregation+tanh, bitonic top-k sort,
// gather, conv1+pool+conv2+dense
// ---------------------------------------------------------------------------
__global__ void k_head(const float* __restrict__ b3,
                       const float* __restrict__ wc1, const float* __restrict__ bc1,
                       const float* __restrict__ wc2, const float* __restrict__ bc2,
                       const float* __restrict__ wout, const float* __restrict__ bout,
                       float* __restrict__ out){
    __shared__ float s_val[NPG];
    __shared__ int   s_idx[NPG];
    __shared__ float s_sp[KTOP*DLAT];
    __shared__ float s_w1[C1*DLAT];
    __shared__ float s_t1[C1*30];
    __shared__ float s_p[C1*15];
    __shared__ float s_q[C2*11];
    int b = blockIdx.x, tid = threadIdx.x;
    float bias3 = __ldg(&b3[0]);
    for (int i = tid; i < NPG; i += blockDim.x){
        int node = b*NPG + i;
        int s = g_rowptr[node], e = g_rowptr[node+1];
        float acc = g_Z[node];
        for (int j = s; j < e; j++) acc += g_Z[__ldg(&g_csr[j])];
        float h = tanhf((acc + bias3) / (float)(e - s + 1));
        g_feat[(size_t)node*DLAT + 96] = h;
        s_val[i] = h;
        s_idx[i] = i;
    }
    for (int i = tid; i < C1*DLAT; i += blockDim.x) s_w1[i] = wc1[i];
    __syncthreads();
    // bitonic sort: descending by val, ties -> ascending index
    for (int k = 2; k <= NPG; k <<= 1){
        for (int j = k >> 1; j > 0; j >>= 1){
            for (int i = tid; i < NPG; i += blockDim.x){
                int ixj = i ^ j;
                if (ixj > i){
                    float va = s_val[i], vb = s_val[ixj];
                    int ia = s_idx[i], ib = s_idx[ixj];
                    bool before_ba = (vb > va) || (vb == va && ib < ia);
                    bool up = ((i & k) == 0);
                    if (up ? before_ba : !before_ba){
                        s_val[i] = vb; s_val[ixj] = va;
                        s_idx[i] = ib; s_idx[ixj] = ia;
                    }
                }
            }
            __syncthreads();
        }
    }
    for (int t = tid; t < KTOP*DLAT; t += blockDim.x){
        int kk = t / DLAT, d = t % DLAT;
        int node = b*NPG + s_idx[kk];
        s_sp[t] = g_feat[(size_t)node*DLAT + d];
    }
    __syncthreads();
    for (int t = tid; t < C1*30; t += blockDim.x){
        int c = t / 30, j = t % 30;
        float acc = bc1[c];
        for (int d = 0; d < DLAT; d++) acc = fmaf(s_sp[j*DLAT + d], s_w1[c*DLAT + d], acc);
        s_t1[t] = fmaxf(acc, 0.f);
    }
    __syncthreads();
    for (int t = tid; t < C1*15; t += blockDim.x){
        int c = t / 15, l = t % 15;
        s_p[t] = fmaxf(s_t1[c*30 + 2*l], s_t1[c*30 + 2*l + 1]);
    }
    __syncthreads();
    for (int t = tid; t < C2*11; t += blockDim.x){
        int c2 = t / 11, l = t % 11;
        float acc = bc2[c2];
        for (int c1 = 0; c1 < C1; c1++)
            #pragma unroll
            for (int tt = 0; tt < KW2; tt++)
                acc = fmaf(s_p[c1*15 + l + tt], wc2[(c2*C1 + c1)*KW2 + tt], acc);
        s_q[t] = fmaxf(acc, 0.f);
    }
    __syncthreads();
    if (tid < 64){
        int o = tid >> 5, lane = tid & 31;
        float acc = 0.f;
        for (int i = lane; i < C2*11; i += 32) acc = fmaf(s_q[i], wout[i*OUTC + o], acc);
        #pragma unroll
        for (int s = 16; s > 0; s >>= 1) acc += __shfl_xor_sync(0xffffffffu, acc, s);
        if (lane == 0) out[b*OUTC + o] = fmaxf(acc + bout[o], 0.f);
    }
}

extern "C" void kernel_launch(void* const* d_in, const int* in_sizes, int n_in,
                              void* d_out, int out_size){
    const float* nf   = (const float*)d_in[0];
    const float* ef   = (const float*)d_in[1];
    const int*   ei   = (const int*)  d_in[2];
    const float* W0   = (const float*)d_in[3];
    const float* b0   = (const float*)d_in[4];
    const float* W1   = (const float*)d_in[5];
    const float* b1   = (const float*)d_in[6];
    const float* W2   = (const float*)d_in[7];
    const float* b2   = (const float*)d_in[8];
    const float* W3   = (const float*)d_in[9];
    const float* b3   = (const float*)d_in[10];
    const float* wc1  = (const float*)d_in[11];
    const float* bc1  = (const float*)d_in[12];
    const float* wc2  = (const float*)d_in[13];
    const float* bc2  = (const float*)d_in[14];
    const float* wout = (const float*)d_in[15];
    const float* bout = (const float*)d_in[16];
    float* out = (float*)d_out;

    static int configured = 0;
    if (!configured){
        cudaFuncSetAttribute(k_gemm0, cudaFuncAttributeMaxDynamicSharedMemorySize, G0_SMEM);
        configured = 1;
    }

    const int T = 256;
    k_init<<<(NN*32 + T-1)/T, T>>>();
    k_edge<<<(NE*8 + T-1)/T, T>>>(ef, ei);
    // CSR build
    k_scan1<<<128, 1024>>>();
    k_scan2<<<1, 1024>>>();
    k_bin<<<(NE + T-1)/T, T>>>(ei);
    // hop 0 GEMM
    k_gemm0<<<NN/128, 256, G0_SMEM>>>(nf, W0);
    // fused hops
    k_hop<<<NN/32, 256>>>(W1, b0, 0, 0);   // g_Y -> g_Z
    k_hop<<<NN/32, 256>>>(W2, b1, 32, 1);  // g_Z -> g_Y
    k_hopC<<<NN/32, 256>>>(W3, b2);        // g_Y -> g_Z (width-1)
    // fused hop3 finish + sort-pool + conv head
    k_head<<<NB, 1024>>>(b3, wc1, bc1, wc2, bc2, wout, bout, out);
}